// round 4
// baseline (speedup 1.0000x reference)
#include <cuda_runtime.h>
#include <cuda_bf16.h>

// Laplacian-pyramid L1 loss, 5 levels, (32,3,512,512) fp32.
// pyr(in)-pyr(tg) == pyr(in-tg). Reflect padding is scale-consistent ->
// upsample needs only a 1-halo down tile, no refl logic. Fully separable,
// float4-vectorized smem pipeline.

#define BC 96
#define NLVL 5

__device__ __align__(16) float g_scratch[BC * (256*256 + 128*128 + 64*64)];
__device__ double g_sums[NLVL];

__device__ __forceinline__ int refl(int t, int n) {
    if (t < 0)  return -t;
    if (t >= n) return 2*n - 2 - t;
    return t;
}
__device__ __forceinline__ float wt(int i) {
    return (i == 0 || i == 4) ? 1.0f : ((i == 2) ? 6.0f : 4.0f);
}
__device__ __forceinline__ float4 ld4(const float* p) {
    return *reinterpret_cast<const float4*>(p);
}
__device__ __forceinline__ void st4(float* p, float4 v) {
    *reinterpret_cast<float4*>(p) = v;
}

__global__ void zero_sums_kernel() {
    if (threadIdx.x < NLVL) g_sums[threadIdx.x] = 0.0;
}

__device__ __forceinline__ void block_reduce_atomic(float v, int lvl, float* sred) {
    const int tid = threadIdx.x;
#pragma unroll
    for (int o = 16; o; o >>= 1) v += __shfl_down_sync(0xffffffffu, v, o);
    if ((tid & 31) == 0) sred[tid >> 5] = v;
    __syncthreads();
    if (tid < 16) {
        float x = sred[tid];
#pragma unroll
        for (int o = 8; o; o >>= 1) x += __shfl_down_sync(0xffffu, x, o);
        if (tid == 0) atomicAdd(&g_sums[lvl], (double)x);
    }
    __syncthreads();
}

// ---------------- vectorized tiled kernel: levels 0..2 ----------------
template <int TILE, bool DIFF>
__global__ __launch_bounds__(512)
void lvl_kernel(const float* __restrict__ a, const float* __restrict__ b,
                int srcOff, int dstOff, int H, int lvl, int tilesRow)
{
    constexpr int DT = TILE + 8;     // 72: full-res tile + 4-halo
    constexpr int DP = DT + 4;       // 76: padded pitch (16B-aligned rows)
    constexpr int HT = TILE/2 + 2;   // 34: down tile + 1-halo
    constexpr int HP = 36;           // padded pitch
    constexpr int HI = TILE/2;       // 32

    __shared__ float sd [DT * DP];
    __shared__ float st [DT * HP];   // horiz temp; aliased as sup[HT*TILE]
    __shared__ float sdn[HT * HP];
    __shared__ float sred[16];

    const int W = H, h = H >> 1;
    const int tid = threadIdx.x, NT = blockDim.x;
    const int ty = blockIdx.x / tilesRow, tx = blockIdx.x - ty * tilesRow;
    const int bc = blockIdx.y;
    const int y0 = ty * TILE, x0 = tx * TILE;
    const int r0 = y0 >> 1,  c0 = x0 >> 1;

    const float* sa = DIFF ? a + (size_t)bc * H * W
                           : g_scratch + srcOff + (size_t)bc * H * W;
    const float* sb = DIFF ? b + (size_t)bc * H * W : nullptr;

    // ---- load diff tile, float4 fast path, reflect slow path ----
    for (int it = tid; it < DT * (DT/4); it += NT) {
        int ly = it / (DT/4), ck = it - ly * (DT/4);
        int gy  = y0 - 4 + ly;
        int gx0 = x0 - 4 + 4*ck;
        float4 v;
        if (gy >= 0 && gy < H && gx0 >= 0 && gx0 + 3 < W) {
            size_t g = (size_t)gy * W + gx0;
            v = ld4(sa + g);
            if (DIFF) {
                float4 w = ld4(sb + g);
                v.x -= w.x; v.y -= w.y; v.z -= w.z; v.w -= w.w;
            }
        } else {
            int yy = refl(gy, H);
            float t[4];
#pragma unroll
            for (int k = 0; k < 4; k++) {
                int xx = refl(gx0 + k, W);
                size_t g = (size_t)yy * W + xx;
                t[k] = sa[g];
                if (DIFF) t[k] -= sb[g];
            }
            v = make_float4(t[0], t[1], t[2], t[3]);
        }
        st4(sd + ly * DP + 4*ck, v);
    }
    for (int ly = tid; ly < DT; ly += NT)       // zero pad cols DT..DP-1
        st4(sd + ly * DP + DT, make_float4(0.f, 0.f, 0.f, 0.f));
    __syncthreads();

    // ---- horizontal gauss, stride 2: 3 LDS.128 -> 4 outputs ----
    for (int it = tid; it < DT * (HP/4); it += NT) {
        int ly = it / (HP/4), ck = it - ly * (HP/4);
        const float* base = sd + ly * DP + 8*ck;
        float4 A = ld4(base), B = ld4(base + 4), C = ld4(base + 8);
        float v0=A.x,v1=A.y,v2=A.z,v3=A.w,v4=B.x,v5=B.y,v6=B.z,v7=B.w,v8=C.x,v9=C.y,v10=C.z;
        float4 o;
        o.x = v0 + 4.f*v1 + 6.f*v2 + 4.f*v3 + v4;
        o.y = v2 + 4.f*v3 + 6.f*v4 + 4.f*v5 + v6;
        o.z = v4 + 4.f*v5 + 6.f*v6 + 4.f*v7 + v8;
        o.w = v6 + 4.f*v7 + 6.f*v8 + 4.f*v9 + v10;
        st4(st + ly * HP + 4*ck, o);
    }
    __syncthreads();

    // ---- vertical gauss, stride 2: 5 LDS.128 -> 4 outputs ----
    for (int it = tid; it < HT * (HP/4); it += NT) {
        int dr = it / (HP/4), ck = it - dr * (HP/4);
        const float* base = st + (2*dr) * HP + 4*ck;
        float4 r0v = ld4(base), r1v = ld4(base + HP), r2v = ld4(base + 2*HP),
               r3v = ld4(base + 3*HP), r4v = ld4(base + 4*HP);
        float4 o;
        o.x = (r0v.x + 4.f*r1v.x + 6.f*r2v.x + 4.f*r3v.x + r4v.x) * (1.f/256.f);
        o.y = (r0v.y + 4.f*r1v.y + 6.f*r2v.y + 4.f*r3v.y + r4v.y) * (1.f/256.f);
        o.z = (r0v.z + 4.f*r1v.z + 6.f*r2v.z + 4.f*r3v.z + r4v.z) * (1.f/256.f);
        o.w = (r0v.w + 4.f*r1v.w + 6.f*r2v.w + 4.f*r3v.w + r4v.w) * (1.f/256.f);
        st4(sdn + dr * HP + 4*ck, o);
    }
    __syncthreads();

    // ---- write interior down tile (next level source), STG.128 ----
    {
        float* gdn = g_scratch + dstOff + (size_t)bc * h * h;
        for (int it = tid; it < HI * (HI/4); it += NT) {
            int dr = it / (HI/4), ck = it - dr * (HI/4);
            const float* s = sdn + (dr + 1) * HP + 4*ck + 1;
            st4(gdn + (size_t)(r0 + dr) * h + c0 + 4*ck,
                make_float4(s[0], s[1], s[2], s[3]));
        }
    }

    // ---- horizontal upsample: 6 floats -> 8 outputs ----
    float* sup = st;   // st dead after vert pass (sync above)
    for (int it = tid; it < HT * (TILE/8); it += NT) {
        int dr = it / (TILE/8), j = it - dr * (TILE/8);
        const float* dnr = sdn + dr * HP + 4*j;
        float4 A = ld4(dnr);
        float v0=A.x, v1=A.y, v2=A.z, v3=A.w, v4=dnr[4], v5=dnr[5];
        float4 oA, oB;
        oA.x = v0 + 6.f*v1 + v2;  oA.y = 4.f*(v1 + v2);
        oA.z = v1 + 6.f*v2 + v3;  oA.w = 4.f*(v2 + v3);
        oB.x = v2 + 6.f*v3 + v4;  oB.y = 4.f*(v3 + v4);
        oB.z = v3 + 6.f*v4 + v5;  oB.w = 4.f*(v4 + v5);
        st4(sup + dr * TILE + 8*j,     oA);
        st4(sup + dr * TILE + 8*j + 4, oB);
    }
    __syncthreads();

    // ---- vertical upsample + |d - up|, 4 px/thread ----
    float lsum = 0.0f;
    for (int it = tid; it < TILE * (TILE/4); it += NT) {
        int py = it / (TILE/4), ck = it - py * (TILE/4);
        int lr = (py >> 1) + 1;
        const float* s1 = sup + lr * TILE + 4*ck;
        float4 bm = ld4(s1), cm = ld4(s1 + TILE), u;
        if (py & 1) {
            u.x = 4.f*(bm.x + cm.x); u.y = 4.f*(bm.y + cm.y);
            u.z = 4.f*(bm.z + cm.z); u.w = 4.f*(bm.w + cm.w);
        } else {
            float4 am = ld4(s1 - TILE);
            u.x = am.x + 6.f*bm.x + cm.x; u.y = am.y + 6.f*bm.y + cm.y;
            u.z = am.z + 6.f*bm.z + cm.z; u.w = am.w + 6.f*bm.w + cm.w;
        }
        float4 d = ld4(sd + (py + 4) * DP + 4*ck + 4);
        lsum += fabsf(d.x - u.x * (1.f/64.f)) + fabsf(d.y - u.y * (1.f/64.f))
              + fabsf(d.z - u.z * (1.f/64.f)) + fabsf(d.w - u.w * (1.f/64.f));
    }
    block_reduce_atomic(lsum, lvl, sred);
}

// ---------------- in-smem level step (whole plane resident) ----------------
__device__ __forceinline__ void level_smem(const float* src, int sStride, int H,
                                           float* st, float* sdn,
                                           float& lsum, int tid, int NT)
{
    const int h = H >> 1, HT2 = h + 2;
    for (int idx = tid; idx < H * HT2; idx += NT) {
        int y = idx / HT2, dc = idx - y * HT2;
        const float* row = src + y * sStride;
        float acc = 0.f;
#pragma unroll
        for (int j = 0; j < 5; j++) acc += wt(j) * row[refl(2*dc - 4 + j, H)];
        st[idx] = acc;
    }
    __syncthreads();
    for (int idx = tid; idx < HT2 * HT2; idx += NT) {
        int dr = idx / HT2, dc = idx - dr * HT2;
        float acc = 0.f;
#pragma unroll
        for (int i = 0; i < 5; i++) acc += wt(i) * st[refl(2*dr - 4 + i, H) * HT2 + dc];
        sdn[idx] = acc * (1.f/256.f);
    }
    __syncthreads();
    float* sup = st;
    for (int idx = tid; idx < HT2 * H; idx += NT) {
        int dr = idx / H, x = idx - dr * H;
        const float* dnr = sdn + dr * HT2;
        int lc = (x >> 1) + 1;
        sup[idx] = (x & 1) ? 4.f * (dnr[lc] + dnr[lc + 1])
                           : dnr[lc - 1] + 6.f * dnr[lc] + dnr[lc + 1];
    }
    __syncthreads();
    for (int idx = tid; idx < H * H; idx += NT) {
        int y = idx / H, x = idx - y * H;
        int lr = (y >> 1) + 1;
        float u = (y & 1) ? 4.f * (sup[lr*H + x] + sup[(lr+1)*H + x])
                          : sup[(lr-1)*H + x] + 6.f*sup[lr*H + x] + sup[(lr+1)*H + x];
        lsum += fabsf(src[y * sStride + x] - u * (1.f/64.f));
    }
    __syncthreads();
}

// ---------------- fused levels 3+4: one block per bc-plane ----------------
__global__ __launch_bounds__(512)
void tail_kernel(int srcOff)
{
    __shared__ float sa  [64 * 64];
    __shared__ float st3 [64 * 34];
    __shared__ float sdn3[34 * 34];
    __shared__ float st4m[32 * 18];
    __shared__ float sdn4[18 * 18];
    __shared__ float sred[16];

    const int tid = threadIdx.x, NT = blockDim.x;
    const int bc = blockIdx.x;

    const float* g = g_scratch + srcOff + (size_t)bc * 64 * 64;
    for (int idx = tid; idx < 64 * 64 / 4; idx += NT)
        st4(sa + 4*idx, ld4(g + 4*idx));
    __syncthreads();

    float l3 = 0.f, l4 = 0.f;
    level_smem(sa, 64, 64, st3, sdn3, l3, tid, NT);
    block_reduce_atomic(l3, 3, sred);
    level_smem(sdn3 + 34 + 1, 34, 32, st4m, sdn4, l4, tid, NT);
    block_reduce_atomic(l4, 4, sred);
}

__global__ void finalize_kernel(float* out) {
    if (threadIdx.x == 0 && blockIdx.x == 0) {
        double tot = 0.0;
        const int hs[NLVL] = {512, 256, 128, 64, 32};
#pragma unroll
        for (int l = 0; l < NLVL; l++) {
            double numel = (double)BC * hs[l] * hs[l];
            tot += g_sums[l] / numel;
        }
        out[0] = (float)tot;
    }
}

extern "C" void kernel_launch(void* const* d_in, const int* in_sizes, int n_in,
                              void* d_out, int out_size) {
    const float* input  = (const float*)d_in[0];
    const float* target = (const float*)d_in[1];
    float* out = (float*)d_out;

    const int OFF0 = 0;
    const int OFF1 = BC * 256*256;
    const int OFF2 = BC * 256*256 + BC * 128*128;

    zero_sums_kernel<<<1, 32>>>();

    lvl_kernel<64, true ><<<dim3(64, BC), 512>>>(input,  target,  0,    OFF0, 512, 0, 8);
    lvl_kernel<64, false><<<dim3(16, BC), 512>>>(nullptr, nullptr, OFF0, OFF1, 256, 1, 4);
    lvl_kernel<64, false><<<dim3(4,  BC), 512>>>(nullptr, nullptr, OFF1, OFF2, 128, 2, 2);
    tail_kernel<<<BC, 512>>>(OFF2);

    finalize_kernel<<<1, 32>>>(out);
}

// round 5
// speedup vs baseline: 1.6907x; 1.6907x over previous
#include <cuda_runtime.h>
#include <cuda_bf16.h>

// Laplacian-pyramid L1 loss, 5 levels, (32,3,512,512) fp32.
// pyr(in)-pyr(tg) == pyr(in-tg). Reflect padding is scale-consistent ->
// upsample needs only a 1-halo down tile, no refl logic. Separable pipeline.
// R5: scalar smem where stride-2 (conflict-prone), float4 where contiguous.

#define BC 96
#define NLVL 5

__device__ __align__(16) float g_scratch[BC * (256*256 + 128*128 + 64*64)];
__device__ double g_sums[NLVL];

__device__ __forceinline__ int refl(int t, int n) {
    if (t < 0)  return -t;
    if (t >= n) return 2*n - 2 - t;
    return t;
}
__device__ __forceinline__ float wt(int i) {
    return (i == 0 || i == 4) ? 1.0f : ((i == 2) ? 6.0f : 4.0f);
}
__device__ __forceinline__ float4 ld4(const float* p) {
    return *reinterpret_cast<const float4*>(p);
}
__device__ __forceinline__ void st4(float* p, float4 v) {
    *reinterpret_cast<float4*>(p) = v;
}

__global__ void zero_sums_kernel() {
    if (threadIdx.x < NLVL) g_sums[threadIdx.x] = 0.0;
}

__device__ __forceinline__ void block_reduce_atomic(float v, int lvl, float* sred) {
    const int tid = threadIdx.x;
#pragma unroll
    for (int o = 16; o; o >>= 1) v += __shfl_down_sync(0xffffffffu, v, o);
    if ((tid & 31) == 0) sred[tid >> 5] = v;
    __syncthreads();
    if (tid < 16) {
        float x = sred[tid];
#pragma unroll
        for (int o = 8; o; o >>= 1) x += __shfl_down_sync(0xffffu, x, o);
        if (tid == 0) atomicAdd(&g_sums[lvl], (double)x);
    }
    __syncthreads();
}

// ---------------- tiled kernel: levels 0..2 (TILE=64, 512 thr) ----------------
template <int TILE, bool DIFF>
__global__ __launch_bounds__(512)
void lvl_kernel(const float* __restrict__ a, const float* __restrict__ b,
                int srcOff, int dstOff, int H, int lvl, int tilesRow)
{
    constexpr int DT = TILE + 8;      // 72
    constexpr int DC = DT / 4;        // 18 float4 chunks per row
    constexpr int HT = TILE/2 + 2;    // 34
    constexpr int HP = 36;            // padded pitch for st/sdn
    constexpr int HC = HP / 4;        // 9
    constexpr int HI = TILE/2;        // 32
    constexpr int NT = 512;

    __shared__ float sd [DT * DT];    // pitch DT=72 (div 4 -> rows 16B aligned)
    __shared__ float st [DT * HP];    // horiz temp; aliased later as sup[HT*TILE]
    __shared__ float sdn[HT * HP];
    __shared__ float sred[16];

    const int W = H, h = H >> 1;
    const int tid = threadIdx.x;
    const int ty = blockIdx.x / tilesRow, tx = blockIdx.x - ty * tilesRow;
    const int bc = blockIdx.y;
    const int y0 = ty * TILE, x0 = tx * TILE;
    const int r0 = y0 >> 1,  c0 = x0 >> 1;

    const float* sa = DIFF ? a + (size_t)bc * H * W
                           : g_scratch + srcOff + (size_t)bc * H * W;
    const float* sb = DIFF ? b + (size_t)bc * H * W : nullptr;

    // ---- load diff tile: float4 fast path, reflect slow path ----
    {
        int row = tid / DC, col = tid - row * DC;
        constexpr int dR = NT / DC, dC = NT % DC;   // 28, 8
        for (int it = tid; it < DT * DC; it += NT) {
            int gy  = y0 - 4 + row;
            int gx0 = x0 - 4 + 4 * col;
            float4 v;
            if (gy >= 0 && gy < H && gx0 >= 0 && gx0 + 3 < W) {
                size_t g = (size_t)gy * W + gx0;
                v = ld4(sa + g);
                if (DIFF) {
                    float4 w = ld4(sb + g);
                    v.x -= w.x; v.y -= w.y; v.z -= w.z; v.w -= w.w;
                }
            } else {
                int yy = refl(gy, H);
                float t[4];
#pragma unroll
                for (int k = 0; k < 4; k++) {
                    int xx = refl(gx0 + k, W);
                    size_t g = (size_t)yy * W + xx;
                    t[k] = sa[g];
                    if (DIFF) t[k] -= sb[g];
                }
                v = make_float4(t[0], t[1], t[2], t[3]);
            }
            st4(sd + row * DT + 4 * col, v);
            row += dR; col += dC;
            if (col >= DC) { col -= DC; row++; }
        }
    }
    __syncthreads();

    // ---- horizontal gauss, stride 2 (scalar: conflict-free broadcastish) ----
    {
        int r = tid / HT, c = tid - r * HT;
        constexpr int dR = NT / HT, dC = NT % HT;   // 15, 2
        for (int it = tid; it < DT * HT; it += NT) {
            const float* p = sd + r * DT + 2 * c;
            st[r * HP + c] = p[0] + 4.f*p[1] + 6.f*p[2] + 4.f*p[3] + p[4];
            r += dR; c += dC;
            if (c >= HT) { c -= HT; r++; }
        }
    }
    __syncthreads();

    // ---- vertical gauss, stride 2 (float4: contiguous 16B/thread) ----
    {
        int r = tid / HC, ck = tid - r * HC;
        constexpr int dR = NT / HC, dC = NT % HC;   // 56, 8
        for (int it = tid; it < HT * HC; it += NT) {
            const float* base = st + (2 * r) * HP + 4 * ck;
            float4 r0v = ld4(base),          r1v = ld4(base + HP),
                   r2v = ld4(base + 2*HP),   r3v = ld4(base + 3*HP),
                   r4v = ld4(base + 4*HP);
            float4 o;
            o.x = (r0v.x + 4.f*r1v.x + 6.f*r2v.x + 4.f*r3v.x + r4v.x) * (1.f/256.f);
            o.y = (r0v.y + 4.f*r1v.y + 6.f*r2v.y + 4.f*r3v.y + r4v.y) * (1.f/256.f);
            o.z = (r0v.z + 4.f*r1v.z + 6.f*r2v.z + 4.f*r3v.z + r4v.z) * (1.f/256.f);
            o.w = (r0v.w + 4.f*r1v.w + 6.f*r2v.w + 4.f*r3v.w + r4v.w) * (1.f/256.f);
            st4(sdn + r * HP + 4 * ck, o);
            r += dR; ck += dC;
            if (ck >= HC) { ck -= HC; r++; }
        }
    }
    __syncthreads();

    // ---- write interior down tile: scalar smem reads, STG.128 ----
    {
        float* gdn = g_scratch + dstOff + (size_t)bc * h * h;
        constexpr int WC = HI / 4;                  // 8
        int r = tid / WC, ck = tid - r * WC;
        constexpr int dR = NT / WC, dC = NT % WC;   // 64, 0
        for (int it = tid; it < HI * WC; it += NT) {
            const float* s = sdn + (r + 1) * HP + 4 * ck + 1;
            st4(gdn + (size_t)(r0 + r) * h + c0 + 4 * ck,
                make_float4(s[0], s[1], s[2], s[3]));
            r += dR; ck += dC;
            if (ck >= WC) { ck -= WC; r++; }
        }
    }

    // ---- horizontal upsample (scalar; sdn reads broadcast-friendly) ----
    float* sup = st;   // st dead after vgauss sync
    for (int it = tid; it < HT * TILE; it += NT) {
        int r = it / TILE, x = it - r * TILE;       // TILE pow2 -> shifts
        const float* dnr = sdn + r * HP;
        int lc = (x >> 1) + 1;
        sup[r * TILE + x] = (x & 1) ? 4.f * (dnr[lc] + dnr[lc + 1])
                                    : dnr[lc - 1] + 6.f * dnr[lc] + dnr[lc + 1];
    }
    __syncthreads();

    // ---- vertical upsample + |d - up| (float4: contiguous 16B/thread) ----
    float lsum = 0.0f;
    {
        constexpr int TC = TILE / 4;                // 16, pow2
        for (int it = tid; it < TILE * TC; it += NT) {
            int py = it / TC, ck = it - py * TC;    // shifts
            int lr = (py >> 1) + 1;
            const float* s1 = sup + lr * TILE + 4 * ck;
            float4 bm = ld4(s1), cm = ld4(s1 + TILE), u;
            if (py & 1) {
                u.x = 4.f*(bm.x + cm.x); u.y = 4.f*(bm.y + cm.y);
                u.z = 4.f*(bm.z + cm.z); u.w = 4.f*(bm.w + cm.w);
            } else {
                float4 am = ld4(s1 - TILE);
                u.x = am.x + 6.f*bm.x + cm.x; u.y = am.y + 6.f*bm.y + cm.y;
                u.z = am.z + 6.f*bm.z + cm.z; u.w = am.w + 6.f*bm.w + cm.w;
            }
            float4 d = ld4(sd + (py + 4) * DT + 4 * ck + 4);
            lsum += fabsf(d.x - u.x * (1.f/64.f)) + fabsf(d.y - u.y * (1.f/64.f))
                  + fabsf(d.z - u.z * (1.f/64.f)) + fabsf(d.w - u.w * (1.f/64.f));
        }
    }
    block_reduce_atomic(lsum, lvl, sred);
}

// ---------------- in-smem level step (whole plane resident) ----------------
__device__ __forceinline__ void level_smem(const float* src, int sStride, int H,
                                           float* st, float* sdn,
                                           float& lsum, int tid, int NT)
{
    const int h = H >> 1, HT2 = h + 2;
    for (int idx = tid; idx < H * HT2; idx += NT) {
        int y = idx / HT2, dc = idx - y * HT2;
        const float* row = src + y * sStride;
        float acc = 0.f;
#pragma unroll
        for (int j = 0; j < 5; j++) acc += wt(j) * row[refl(2*dc - 4 + j, H)];
        st[idx] = acc;
    }
    __syncthreads();
    for (int idx = tid; idx < HT2 * HT2; idx += NT) {
        int dr = idx / HT2, dc = idx - dr * HT2;
        float acc = 0.f;
#pragma unroll
        for (int i = 0; i < 5; i++) acc += wt(i) * st[refl(2*dr - 4 + i, H) * HT2 + dc];
        sdn[idx] = acc * (1.f/256.f);
    }
    __syncthreads();
    float* sup = st;
    for (int idx = tid; idx < HT2 * H; idx += NT) {
        int dr = idx / H, x = idx - dr * H;
        const float* dnr = sdn + dr * HT2;
        int lc = (x >> 1) + 1;
        sup[idx] = (x & 1) ? 4.f * (dnr[lc] + dnr[lc + 1])
                           : dnr[lc - 1] + 6.f * dnr[lc] + dnr[lc + 1];
    }
    __syncthreads();
    for (int idx = tid; idx < H * H; idx += NT) {
        int y = idx / H, x = idx - y * H;
        int lr = (y >> 1) + 1;
        float u = (y & 1) ? 4.f * (sup[lr*H + x] + sup[(lr+1)*H + x])
                          : sup[(lr-1)*H + x] + 6.f*sup[lr*H + x] + sup[(lr+1)*H + x];
        lsum += fabsf(src[y * sStride + x] - u * (1.f/64.f));
    }
    __syncthreads();
}

// ---------------- fused levels 3+4: one block per bc-plane ----------------
__global__ __launch_bounds__(512)
void tail_kernel(int srcOff)
{
    __shared__ float sa  [64 * 64];
    __shared__ float st3 [64 * 34];
    __shared__ float sdn3[34 * 34];
    __shared__ float st4m[32 * 18];
    __shared__ float sdn4[18 * 18];
    __shared__ float sred[16];

    const int tid = threadIdx.x, NT = blockDim.x;
    const int bc = blockIdx.x;

    const float* g = g_scratch + srcOff + (size_t)bc * 64 * 64;
    for (int idx = tid; idx < 64 * 64 / 4; idx += NT)
        st4(sa + 4*idx, ld4(g + 4*idx));
    __syncthreads();

    float l3 = 0.f, l4 = 0.f;
    level_smem(sa, 64, 64, st3, sdn3, l3, tid, NT);
    block_reduce_atomic(l3, 3, sred);
    level_smem(sdn3 + 34 + 1, 34, 32, st4m, sdn4, l4, tid, NT);
    block_reduce_atomic(l4, 4, sred);
}

__global__ void finalize_kernel(float* out) {
    if (threadIdx.x == 0 && blockIdx.x == 0) {
        double tot = 0.0;
        const int hs[NLVL] = {512, 256, 128, 64, 32};
#pragma unroll
        for (int l = 0; l < NLVL; l++) {
            double numel = (double)BC * hs[l] * hs[l];
            tot += g_sums[l] / numel;
        }
        out[0] = (float)tot;
    }
}

extern "C" void kernel_launch(void* const* d_in, const int* in_sizes, int n_in,
                              void* d_out, int out_size) {
    const float* input  = (const float*)d_in[0];
    const float* target = (const float*)d_in[1];
    float* out = (float*)d_out;

    const int OFF0 = 0;
    const int OFF1 = BC * 256*256;
    const int OFF2 = BC * 256*256 + BC * 128*128;

    zero_sums_kernel<<<1, 32>>>();

    lvl_kernel<64, true ><<<dim3(64, BC), 512>>>(input,  target,  0,    OFF0, 512, 0, 8);
    lvl_kernel<64, false><<<dim3(16, BC), 512>>>(nullptr, nullptr, OFF0, OFF1, 256, 1, 4);
    lvl_kernel<64, false><<<dim3(4,  BC), 512>>>(nullptr, nullptr, OFF1, OFF2, 128, 2, 2);
    tail_kernel<<<BC, 512>>>(OFF2);

    finalize_kernel<<<1, 32>>>(out);
}

// round 6
// speedup vs baseline: 1.7041x; 1.0079x over previous
#include <cuda_runtime.h>
#include <cuda_bf16.h>

// Laplacian-pyramid L1 loss, 5 levels, (32,3,512,512) fp32.
// pyr(in)-pyr(tg) == pyr(in-tg); reflect padding is scale-consistent so the
// upsample needs only a 1-halo down tile. R6: even/odd column deinterleave ->
// every smem phase is unit-stride, conflict-free, float4.

#define BC 96
#define NLVL 5

__device__ __align__(16) float g_scratch[BC * (256*256 + 128*128 + 64*64)];
__device__ double g_sums[NLVL];

__device__ __forceinline__ int refl(int t, int n) {
    if (t < 0)  return -t;
    if (t >= n) return 2*n - 2 - t;
    return t;
}
__device__ __forceinline__ float wt(int i) {
    return (i == 0 || i == 4) ? 1.0f : ((i == 2) ? 6.0f : 4.0f);
}
__device__ __forceinline__ float4 ld4(const float* p) {
    return *reinterpret_cast<const float4*>(p);
}
__device__ __forceinline__ void st4(float* p, float4 v) {
    *reinterpret_cast<float4*>(p) = v;
}
__device__ __forceinline__ float2 ld2(const float* p) {
    return *reinterpret_cast<const float2*>(p);
}
__device__ __forceinline__ void st2(float* p, float2 v) {
    *reinterpret_cast<float2*>(p) = v;
}

__global__ void zero_sums_kernel() {
    if (threadIdx.x < NLVL) g_sums[threadIdx.x] = 0.0;
}

__device__ __forceinline__ void block_reduce_atomic(float v, int lvl, float* sred) {
    const int tid = threadIdx.x;
#pragma unroll
    for (int o = 16; o; o >>= 1) v += __shfl_down_sync(0xffffffffu, v, o);
    if ((tid & 31) == 0) sred[tid >> 5] = v;
    __syncthreads();
    if (tid < 16) {
        float x = sred[tid];
#pragma unroll
        for (int o = 8; o; o >>= 1) x += __shfl_down_sync(0xffffu, x, o);
        if (tid == 0) atomicAdd(&g_sums[lvl], (double)x);
    }
    __syncthreads();
}

// ---------------- tiled kernel: levels 0..2 (TILE=64, 512 thr) ----------------
template <bool DIFF>
__global__ __launch_bounds__(512)
void lvl_kernel(const float* __restrict__ a, const float* __restrict__ b,
                int srcOff, int dstOff, int H, int lvl, int tilesRow)
{
    constexpr int TILE = 64;
    constexpr int DT = 72;            // full-res rows (tile + 4-halo)
    constexpr int DC = 18;            // float4 chunks per full-res row
    constexpr int PE = 40;            // pitch of sdE/sdO (36 used + pad, 160B)
    constexpr int HT = 34;            // down rows (+1-halo)
    constexpr int HP = 36;            // st/sdn pitch
    constexpr int HI = 32;            // down interior
    constexpr int NT = 512;

    __shared__ float sdE[DT * PE];    // even full-res columns
    __shared__ float sdO[DT * PE];    // odd  full-res columns
    __shared__ float st [DT * HP];    // hgauss temp; later supE[34*32]+supO[34*32]
    __shared__ float sdn[HT * HP];
    __shared__ float sred[16];

    const int W = H, h = H >> 1;
    const int tid = threadIdx.x;
    const int ty = blockIdx.x / tilesRow, tx = blockIdx.x - ty * tilesRow;
    const int bc = blockIdx.y;
    const int y0 = ty * TILE, x0 = tx * TILE;
    const int r0 = y0 >> 1,  c0 = x0 >> 1;

    const float* sa = DIFF ? a + (size_t)bc * H * W
                           : g_scratch + srcOff + (size_t)bc * H * W;
    const float* sb = DIFF ? b + (size_t)bc * H * W : nullptr;

    // ---- load diff tile, deinterleave even/odd columns ----
    {
        int row = tid / DC, col = tid - row * DC;
        constexpr int dR = NT / DC, dC = NT % DC;   // 28, 8
        for (int it = tid; it < DT * DC; it += NT) {
            int gy  = y0 - 4 + row;
            int gx0 = x0 - 4 + 4 * col;
            float4 v;
            if (gy >= 0 && gy < H && gx0 >= 0 && gx0 + 3 < W) {
                size_t g = (size_t)gy * W + gx0;
                v = ld4(sa + g);
                if (DIFF) {
                    float4 w = ld4(sb + g);
                    v.x -= w.x; v.y -= w.y; v.z -= w.z; v.w -= w.w;
                }
            } else {
                int yy = refl(gy, H);
                float t[4];
#pragma unroll
                for (int k = 0; k < 4; k++) {
                    int xx = refl(gx0 + k, W);
                    size_t g = (size_t)yy * W + xx;
                    t[k] = sa[g];
                    if (DIFF) t[k] -= sb[g];
                }
                v = make_float4(t[0], t[1], t[2], t[3]);
            }
            st2(sdE + row * PE + 2 * col, make_float2(v.x, v.z));
            st2(sdO + row * PE + 2 * col, make_float2(v.y, v.w));
            row += dR; col += dC;
            if (col >= DC) { col -= DC; row++; }
        }
    }
    __syncthreads();

    // ---- horizontal gauss, stride 2 via parity arrays (conflict-free f4) ----
    // st[r][c] = E[c] + 6E[c+1] + E[c+2] + 4(O[c] + O[c+1])
    {
        int r = tid / 9, k = tid - (tid / 9) * 9;
        constexpr int dR = NT / 9, dC = NT % 9;     // 56, 8
        for (int it = tid; it < DT * 9; it += NT) {
            const float* Er = sdE + r * PE + 4 * k;
            const float* Or = sdO + r * PE + 4 * k;
            float4 Ea = ld4(Er), Eb = ld4(Er + 4);
            float4 Oa = ld4(Or), Ob = ld4(Or + 4);
            float4 o;
            o.x = Ea.x + 6.f*Ea.y + Ea.z + 4.f*(Oa.x + Oa.y);
            o.y = Ea.y + 6.f*Ea.z + Ea.w + 4.f*(Oa.y + Oa.z);
            o.z = Ea.z + 6.f*Ea.w + Eb.x + 4.f*(Oa.z + Oa.w);
            o.w = Ea.w + 6.f*Eb.x + Eb.y + 4.f*(Oa.w + Ob.x);
            st4(st + r * HP + 4 * k, o);
            r += dR; k += dC;
            if (k >= 9) { k -= 9; r++; }
        }
    }
    __syncthreads();

    // ---- vertical gauss, stride 2 (contiguous float4) ----
    for (int it = tid; it < HT * 9; it += NT) {
        int r = it / 9, ck = it - r * 9;
        const float* base = st + (2 * r) * HP + 4 * ck;
        float4 r0v = ld4(base),        r1v = ld4(base + HP),
               r2v = ld4(base + 2*HP), r3v = ld4(base + 3*HP),
               r4v = ld4(base + 4*HP);
        float4 o;
        o.x = (r0v.x + 4.f*r1v.x + 6.f*r2v.x + 4.f*r3v.x + r4v.x) * (1.f/256.f);
        o.y = (r0v.y + 4.f*r1v.y + 6.f*r2v.y + 4.f*r3v.y + r4v.y) * (1.f/256.f);
        o.z = (r0v.z + 4.f*r1v.z + 6.f*r2v.z + 4.f*r3v.z + r4v.z) * (1.f/256.f);
        o.w = (r0v.w + 4.f*r1v.w + 6.f*r2v.w + 4.f*r3v.w + r4v.w) * (1.f/256.f);
        st4(sdn + r * HP + 4 * ck, o);
    }
    __syncthreads();

    // ---- write interior down tile (next level source) ----
    {
        float* gdn = g_scratch + dstOff + (size_t)bc * h * h;
        for (int it = tid; it < HI * 8; it += NT) {
            int r = it >> 3, ck = it & 7;
            const float* s = sdn + (r + 1) * HP + 4 * ck + 1;
            st4(gdn + (size_t)(r0 + r) * h + c0 + 4 * ck,
                make_float4(s[0], s[1], s[2], s[3]));
        }
    }

    // ---- horizontal upsample into parity-split sup (conflict-free f4) ----
    float* supE = st;                 // st dead after vgauss
    float* supO = st + HT * 32;
    for (int it = tid; it < HT * 8; it += NT) {
        int dr = it >> 3, k = it & 7;
        const float* dnr = sdn + dr * HP + 4 * k;
        float4 A = ld4(dnr), B = ld4(dnr + 4);
        float4 e, o;
        e.x = A.x + 6.f*A.y + A.z;  o.x = 4.f*(A.y + A.z);
        e.y = A.y + 6.f*A.z + A.w;  o.y = 4.f*(A.z + A.w);
        e.z = A.z + 6.f*A.w + B.x;  o.z = 4.f*(A.w + B.x);
        e.w = A.w + 6.f*B.x + B.y;  o.w = 4.f*(B.x + B.y);
        st4(supE + dr * 32 + 4 * k, e);
        st4(supO + dr * 32 + 4 * k, o);
    }
    __syncthreads();

    // ---- vertical upsample + |d - up| (8 px/thread, 1 iter/thread) ----
    float lsum = 0.0f;
    for (int it = tid; it < TILE * 8; it += NT) {
        int y = it >> 3, k = it & 7;
        int lr = (y >> 1) + 1;
        const float* pE = supE + lr * 32 + 4 * k;
        const float* pO = supO + lr * 32 + 4 * k;
        float4 uE, uO;
        if (y & 1) {
            float4 bE = ld4(pE), cE = ld4(pE + 32);
            float4 bO = ld4(pO), cO = ld4(pO + 32);
            uE.x = 4.f*(bE.x+cE.x); uE.y = 4.f*(bE.y+cE.y);
            uE.z = 4.f*(bE.z+cE.z); uE.w = 4.f*(bE.w+cE.w);
            uO.x = 4.f*(bO.x+cO.x); uO.y = 4.f*(bO.y+cO.y);
            uO.z = 4.f*(bO.z+cO.z); uO.w = 4.f*(bO.w+cO.w);
        } else {
            float4 aE = ld4(pE - 32), bE = ld4(pE), cE = ld4(pE + 32);
            float4 aO = ld4(pO - 32), bO = ld4(pO), cO = ld4(pO + 32);
            uE.x = aE.x + 6.f*bE.x + cE.x; uE.y = aE.y + 6.f*bE.y + cE.y;
            uE.z = aE.z + 6.f*bE.z + cE.z; uE.w = aE.w + 6.f*bE.w + cE.w;
            uO.x = aO.x + 6.f*bO.x + cO.x; uO.y = aO.y + 6.f*bO.y + cO.y;
            uO.z = aO.z + 6.f*bO.z + cO.z; uO.w = aO.w + 6.f*bO.w + cO.w;
        }
        // interior full-res col x=2j(+1), j=4k..4k+3 -> E/O index j+2
        int off = (y + 4) * PE + 4 * k + 2;
        float2 dEa = ld2(sdE + off), dEb = ld2(sdE + off + 2);
        float2 dOa = ld2(sdO + off), dOb = ld2(sdO + off + 2);
        lsum += fabsf(dEa.x - uE.x*(1.f/64.f)) + fabsf(dEa.y - uE.y*(1.f/64.f))
              + fabsf(dEb.x - uE.z*(1.f/64.f)) + fabsf(dEb.y - uE.w*(1.f/64.f))
              + fabsf(dOa.x - uO.x*(1.f/64.f)) + fabsf(dOa.y - uO.y*(1.f/64.f))
              + fabsf(dOb.x - uO.z*(1.f/64.f)) + fabsf(dOb.y - uO.w*(1.f/64.f));
    }
    block_reduce_atomic(lsum, lvl, sred);
}

// ---------------- in-smem level step (whole plane resident) ----------------
__device__ __forceinline__ void level_smem(const float* src, int sStride, int H,
                                           float* st, float* sdn,
                                           float& lsum, int tid, int NT)
{
    const int h = H >> 1, HT2 = h + 2;
    for (int idx = tid; idx < H * HT2; idx += NT) {
        int y = idx / HT2, dc = idx - y * HT2;
        const float* row = src + y * sStride;
        float acc = 0.f;
#pragma unroll
        for (int j = 0; j < 5; j++) acc += wt(j) * row[refl(2*dc - 4 + j, H)];
        st[idx] = acc;
    }
    __syncthreads();
    for (int idx = tid; idx < HT2 * HT2; idx += NT) {
        int dr = idx / HT2, dc = idx - dr * HT2;
        float acc = 0.f;
#pragma unroll
        for (int i = 0; i < 5; i++) acc += wt(i) * st[refl(2*dr - 4 + i, H) * HT2 + dc];
        sdn[idx] = acc * (1.f/256.f);
    }
    __syncthreads();
    float* sup = st;
    for (int idx = tid; idx < HT2 * H; idx += NT) {
        int dr = idx / H, x = idx - dr * H;
        const float* dnr = sdn + dr * HT2;
        int lc = (x >> 1) + 1;
        sup[idx] = (x & 1) ? 4.f * (dnr[lc] + dnr[lc + 1])
                           : dnr[lc - 1] + 6.f * dnr[lc] + dnr[lc + 1];
    }
    __syncthreads();
    for (int idx = tid; idx < H * H; idx += NT) {
        int y = idx / H, x = idx - y * H;
        int lr = (y >> 1) + 1;
        float u = (y & 1) ? 4.f * (sup[lr*H + x] + sup[(lr+1)*H + x])
                          : sup[(lr-1)*H + x] + 6.f*sup[lr*H + x] + sup[(lr+1)*H + x];
        lsum += fabsf(src[y * sStride + x] - u * (1.f/64.f));
    }
    __syncthreads();
}

// ---------------- fused levels 3+4: one block per bc-plane ----------------
__global__ __launch_bounds__(512)
void tail_kernel(int srcOff)
{
    __shared__ float sa  [64 * 64];
    __shared__ float st3 [64 * 34];
    __shared__ float sdn3[34 * 34];
    __shared__ float st4m[32 * 18];
    __shared__ float sdn4[18 * 18];
    __shared__ float sred[16];

    const int tid = threadIdx.x, NT = blockDim.x;
    const int bc = blockIdx.x;

    const float* g = g_scratch + srcOff + (size_t)bc * 64 * 64;
    for (int idx = tid; idx < 64 * 64 / 4; idx += NT)
        st4(sa + 4*idx, ld4(g + 4*idx));
    __syncthreads();

    float l3 = 0.f, l4 = 0.f;
    level_smem(sa, 64, 64, st3, sdn3, l3, tid, NT);
    block_reduce_atomic(l3, 3, sred);
    level_smem(sdn3 + 34 + 1, 34, 32, st4m, sdn4, l4, tid, NT);
    block_reduce_atomic(l4, 4, sred);
}

__global__ void finalize_kernel(float* out) {
    if (threadIdx.x == 0 && blockIdx.x == 0) {
        double tot = 0.0;
        const int hs[NLVL] = {512, 256, 128, 64, 32};
#pragma unroll
        for (int l = 0; l < NLVL; l++) {
            double numel = (double)BC * hs[l] * hs[l];
            tot += g_sums[l] / numel;
        }
        out[0] = (float)tot;
    }
}

extern "C" void kernel_launch(void* const* d_in, const int* in_sizes, int n_in,
                              void* d_out, int out_size) {
    const float* input  = (const float*)d_in[0];
    const float* target = (const float*)d_in[1];
    float* out = (float*)d_out;

    const int OFF0 = 0;
    const int OFF1 = BC * 256*256;
    const int OFF2 = BC * 256*256 + BC * 128*128;

    zero_sums_kernel<<<1, 32>>>();

    lvl_kernel<true ><<<dim3(64, BC), 512>>>(input,  target,  0,    OFF0, 512, 0, 8);
    lvl_kernel<false><<<dim3(16, BC), 512>>>(nullptr, nullptr, OFF0, OFF1, 256, 1, 4);
    lvl_kernel<false><<<dim3(4,  BC), 512>>>(nullptr, nullptr, OFF1, OFF2, 128, 2, 2);
    tail_kernel<<<BC, 512>>>(OFF2);

    finalize_kernel<<<1, 32>>>(out);
}